// round 1
// baseline (speedup 1.0000x reference)
#include <cuda_runtime.h>

// ---------------------------------------------------------------------------
// Problem constants: x [B=4, V=2, L=8192, D=768], H=12 heads, hd=64, W=512.
// Flat token rows: 65536 total (interleaved b,v); 32768 per view.
// ---------------------------------------------------------------------------
#define DMODEL 768
#define NROWS_TOTAL 65536
#define QKV_SZ 25165824ull      // 32768 * 768

// Scratch (device globals; allocation-free rule)
__device__ float g_y [(size_t)NROWS_TOTAL * DMODEL];   // LN output (reused for LN1/LN2)
__device__ float g_qkv[6 * QKV_SZ];                    // q0,q1,k0,k1,v0,v1 (compact per view)
__device__ float g_o  [2 * QKV_SZ];                    // attention out per module
__device__ float g_x2 [(size_t)NROWS_TOTAL * DMODEL];  // x + att
__device__ float g_h  [(size_t)NROWS_TOTAL * 3072];    // MLP hidden

// Row-address mapping.
//  view == -1 : flat rows (m in [0,65536))
//  view == -2 : compact per-view rows (m in [0,32768)) with seq-roll
//  view >= 0  : per-view rows m=b*8192+l mapped into [B,V,L,*] layout, with roll
__device__ __forceinline__ size_t rowOff(int m, int view, int roll) {
    if (view == -1) return (size_t)m;
    if (view == -2) return (size_t)((m & ~8191) | ((m + roll) & 8191));
    int b = m >> 13;
    int l = (m + roll) & 8191;
    return (size_t)((((b << 1) + view) << 13) + l);
}

// ---------------------------------------------------------------------------
// LayerNorm: one block (192 threads, float4 each) per row of 768.
// ---------------------------------------------------------------------------
__global__ void __launch_bounds__(192)
ln_kernel(const float* __restrict__ x, const float* __restrict__ g,
          const float* __restrict__ b, float* __restrict__ y)
{
    __shared__ float sh[8];
    int row = blockIdx.x;
    int t = threadIdx.x;
    const float4* xr = (const float4*)(x + (size_t)row * DMODEL);
    float4 v = xr[t];

    float s = v.x + v.y + v.z + v.w;
    #pragma unroll
    for (int o = 16; o; o >>= 1) s += __shfl_xor_sync(0xffffffffu, s, o);
    if ((t & 31) == 0) sh[t >> 5] = s;
    __syncthreads();
    s = sh[0] + sh[1] + sh[2] + sh[3] + sh[4] + sh[5];
    float mean = s * (1.0f / 768.0f);

    float dx = v.x - mean, dy = v.y - mean, dz = v.z - mean, dw = v.w - mean;
    float q = dx * dx + dy * dy + dz * dz + dw * dw;
    __syncthreads();
    #pragma unroll
    for (int o = 16; o; o >>= 1) q += __shfl_xor_sync(0xffffffffu, q, o);
    if ((t & 31) == 0) sh[t >> 5] = q;
    __syncthreads();
    q = sh[0] + sh[1] + sh[2] + sh[3] + sh[4] + sh[5];
    float rs = rsqrtf(q * (1.0f / 768.0f) + 1e-5f);

    float4 gg = ((const float4*)g)[t];
    float4 bb = ((const float4*)b)[t];
    float4 o4;
    o4.x = dx * rs * gg.x + bb.x;
    o4.y = dy * rs * gg.y + bb.y;
    o4.z = dz * rs * gg.z + bb.z;
    o4.w = dw * rs * gg.w + bb.w;
    ((float4*)(y + (size_t)row * DMODEL))[t] = o4;
}

// ---------------------------------------------------------------------------
// SGEMM: C[m,n] = sum_k A[m,k] * W[n,k] + bias[n]  (W row-major [N,K])
// 128x128x16 tile, 256 threads, 8x8 per thread, register-staged prefetch.
// Optional GELU epilogue and residual add. A-row/C-row mapping via rowOff.
// ---------------------------------------------------------------------------
__global__ void __launch_bounds__(256)
gemm_kernel(const float* __restrict__ A, const float* __restrict__ W,
            const float* __restrict__ bias, float* __restrict__ C,
            const float* __restrict__ resid,
            int K, int N, int Aview, int ArollSign, int Cview, int actGelu,
            const int* __restrict__ idxp)
{
    __shared__ __align__(16) float As[16][132];
    __shared__ __align__(16) float Bs[16][132];

    int tid = threadIdx.x;
    int bn = blockIdx.x, bm = blockIdx.y;

    int shf = idxp ? ((idxp[0] & 1) << 8) : 0;   // W/2 = 256 if index odd
    int roll = 0;
    if (ArollSign > 0) roll = shf;
    else if (ArollSign < 0) roll = (8192 - shf) & 8191;

    int ar = tid >> 2;          // 0..63
    int ac = (tid & 3) << 2;    // 0,4,8,12

    const float* Ar0 = A + rowOff(bm * 128 + ar,      Aview, roll) * (size_t)K + ac;
    const float* Ar1 = A + rowOff(bm * 128 + ar + 64, Aview, roll) * (size_t)K + ac;
    const float* Wr0 = W + (size_t)(bn * 128 + ar) * K + ac;
    const float* Wr1 = W + (size_t)(bn * 128 + ar + 64) * K + ac;

    float4 pa0 = *(const float4*)Ar0;
    float4 pa1 = *(const float4*)Ar1;
    float4 pb0 = *(const float4*)Wr0;
    float4 pb1 = *(const float4*)Wr1;

    float acc[8][8];
    #pragma unroll
    for (int i = 0; i < 8; i++)
        #pragma unroll
        for (int j = 0; j < 8; j++) acc[i][j] = 0.f;

    int tx = tid & 15, ty = tid >> 4;
    int KT = K >> 4;

    for (int kt = 0; kt < KT; kt++) {
        As[ac + 0][ar]      = pa0.x; As[ac + 1][ar]      = pa0.y;
        As[ac + 2][ar]      = pa0.z; As[ac + 3][ar]      = pa0.w;
        As[ac + 0][ar + 64] = pa1.x; As[ac + 1][ar + 64] = pa1.y;
        As[ac + 2][ar + 64] = pa1.z; As[ac + 3][ar + 64] = pa1.w;
        Bs[ac + 0][ar]      = pb0.x; Bs[ac + 1][ar]      = pb0.y;
        Bs[ac + 2][ar]      = pb0.z; Bs[ac + 3][ar]      = pb0.w;
        Bs[ac + 0][ar + 64] = pb1.x; Bs[ac + 1][ar + 64] = pb1.y;
        Bs[ac + 2][ar + 64] = pb1.z; Bs[ac + 3][ar + 64] = pb1.w;
        __syncthreads();

        if (kt + 1 < KT) {
            int off = (kt + 1) << 4;
            pa0 = *(const float4*)(Ar0 + off);
            pa1 = *(const float4*)(Ar1 + off);
            pb0 = *(const float4*)(Wr0 + off);
            pb1 = *(const float4*)(Wr1 + off);
        }

        #pragma unroll
        for (int k = 0; k < 16; k++) {
            float4 a0 = *(const float4*)&As[k][ty * 8];
            float4 a1 = *(const float4*)&As[k][ty * 8 + 4];
            float4 b0 = *(const float4*)&Bs[k][tx * 8];
            float4 b1 = *(const float4*)&Bs[k][tx * 8 + 4];
            float av[8] = {a0.x, a0.y, a0.z, a0.w, a1.x, a1.y, a1.z, a1.w};
            float bv[8] = {b0.x, b0.y, b0.z, b0.w, b1.x, b1.y, b1.z, b1.w};
            #pragma unroll
            for (int i = 0; i < 8; i++)
                #pragma unroll
                for (int j = 0; j < 8; j++)
                    acc[i][j] += av[i] * bv[j];
        }
        __syncthreads();
    }

    #pragma unroll
    for (int i = 0; i < 8; i++) {
        int m = bm * 128 + ty * 8 + i;
        size_t cb = rowOff(m, Cview, 0) * (size_t)N;
        #pragma unroll
        for (int j = 0; j < 8; j += 4) {
            int n = bn * 128 + tx * 8 + j;
            float4 bv = *(const float4*)(bias + n);
            float4 v;
            v.x = acc[i][j + 0] + bv.x;
            v.y = acc[i][j + 1] + bv.y;
            v.z = acc[i][j + 2] + bv.z;
            v.w = acc[i][j + 3] + bv.w;
            if (actGelu) {
                v.x = v.x / (1.f + __expf(-1.702f * v.x));
                v.y = v.y / (1.f + __expf(-1.702f * v.y));
                v.z = v.z / (1.f + __expf(-1.702f * v.z));
                v.w = v.w / (1.f + __expf(-1.702f * v.w));
            }
            if (resid) {
                float4 r = *(const float4*)(resid + cb + n);
                v.x += r.x; v.y += r.y; v.z += r.z; v.w += r.w;
            }
            *(float4*)(C + cb + n) = v;
        }
    }
}

// ---------------------------------------------------------------------------
// Flash attention: one block = (module, b, window, head, 64-row q-tile).
// TQ=TK=64, hd=64, 128 threads. K/V share one smem buffer; online softmax.
//  S-phase: thread (t) owns rows r0=(t>>3)*4..+3, cols c0=(t&7)*8..+7
//  O-phase: thread owns row t>>1, d-chunks 8j+4*(t&1)
// ---------------------------------------------------------------------------
__global__ void __launch_bounds__(128)
attn_kernel()
{
    extern __shared__ __align__(16) float smx[];
    float* Qs  = smx;               // [64 k][64 r]
    float* KVs = Qs + 4096;         // K: [64 k][64 c]  then V: [64 c][64 d]
    float* Ps  = KVs + 4096;        // [64 r][65]
    float* rowmax_s = Ps + 4160;    // [64]
    float* rowsum_s = rowmax_s + 64;// [64]
    float* m_s      = rowsum_s + 64;// [64]

    int t  = threadIdx.x;
    int qt = blockIdx.x;            // 0..7
    int hd = blockIdx.y;            // 0..11
    int z  = blockIdx.z;            // 0..127
    int mod = z >> 6;
    int b   = (z >> 4) & 3;
    int w   = z & 15;

    const float* Qb = g_qkv + (size_t)(0 + mod) * QKV_SZ;
    const float* Kb = g_qkv + (size_t)(2 + mod) * QKV_SZ;
    const float* Vb = g_qkv + (size_t)(4 + mod) * QKV_SZ;
    float* Ob = g_o + (size_t)mod * QKV_SZ;

    int winTok = b * 8192 + w * 512;
    int qTok = winTok + qt * 64;
    int hOff = hd * 64;

    // Load Q tile transposed, pre-scaled by 1/sqrt(64)
    for (int idx = t; idx < 1024; idx += 128) {
        int rr = idx >> 4;
        int c4 = (idx & 15) << 2;
        float4 v = *(const float4*)(Qb + (size_t)(qTok + rr) * 768 + hOff + c4);
        Qs[(c4 + 0) * 64 + rr] = v.x * 0.125f;
        Qs[(c4 + 1) * 64 + rr] = v.y * 0.125f;
        Qs[(c4 + 2) * 64 + rr] = v.z * 0.125f;
        Qs[(c4 + 3) * 64 + rr] = v.w * 0.125f;
    }
    if (t < 64) m_s[t] = -1e30f;

    float4 Oc[8];
    #pragma unroll
    for (int j = 0; j < 8; j++) Oc[j] = make_float4(0.f, 0.f, 0.f, 0.f);
    float l_r = 0.f;

    int r0 = (t >> 3) << 2;
    int c0 = (t & 7) << 3;
    int orow = t >> 1;
    int op = t & 1;

    __syncthreads();

    for (int kt = 0; kt < 8; kt++) {
        int kTok = winTok + kt * 64;
        // load K (transposed [k][c])
        for (int idx = t; idx < 1024; idx += 128) {
            int rr = idx >> 4;
            int c4 = (idx & 15) << 2;
            float4 v = *(const float4*)(Kb + (size_t)(kTok + rr) * 768 + hOff + c4);
            KVs[(c4 + 0) * 64 + rr] = v.x;
            KVs[(c4 + 1) * 64 + rr] = v.y;
            KVs[(c4 + 2) * 64 + rr] = v.z;
            KVs[(c4 + 3) * 64 + rr] = v.w;
        }
        __syncthreads();   // K ready

        float S[4][8];
        #pragma unroll
        for (int i = 0; i < 4; i++)
            #pragma unroll
            for (int j = 0; j < 8; j++) S[i][j] = 0.f;

        #pragma unroll 16
        for (int k = 0; k < 64; k++) {
            float4 q  = *(const float4*)&Qs[k * 64 + r0];
            float4 k0 = *(const float4*)&KVs[k * 64 + c0];
            float4 k1 = *(const float4*)&KVs[k * 64 + c0 + 4];
            float qq[4] = {q.x, q.y, q.z, q.w};
            float kk[8] = {k0.x, k0.y, k0.z, k0.w, k1.x, k1.y, k1.z, k1.w};
            #pragma unroll
            for (int i = 0; i < 4; i++)
                #pragma unroll
                for (int j = 0; j < 8; j++)
                    S[i][j] += qq[i] * kk[j];
        }

        #pragma unroll
        for (int i = 0; i < 4; i++) {
            float rm = S[i][0];
            #pragma unroll
            for (int j = 1; j < 8; j++) rm = fmaxf(rm, S[i][j]);
            rm = fmaxf(rm, __shfl_xor_sync(0xffffffffu, rm, 1));
            rm = fmaxf(rm, __shfl_xor_sync(0xffffffffu, rm, 2));
            rm = fmaxf(rm, __shfl_xor_sync(0xffffffffu, rm, 4));
            if ((t & 7) == 0) rowmax_s[r0 + i] = rm;
        }
        __syncthreads();   // rowmax ready; all done reading K

        #pragma unroll
        for (int i = 0; i < 4; i++) {
            float mnew = fmaxf(m_s[r0 + i], rowmax_s[r0 + i]);
            float rs = 0.f;
            #pragma unroll
            for (int j = 0; j < 8; j++) {
                float p = __expf(S[i][j] - mnew);
                Ps[(r0 + i) * 65 + c0 + j] = p;
                rs += p;
            }
            rs += __shfl_xor_sync(0xffffffffu, rs, 1);
            rs += __shfl_xor_sync(0xffffffffu, rs, 2);
            rs += __shfl_xor_sync(0xffffffffu, rs, 4);
            if ((t & 7) == 0) rowsum_s[r0 + i] = rs;
        }
        // load V (direct [c][d]) into the same buffer (K readers done)
        for (int idx = t; idx < 1024; idx += 128) {
            int rr = idx >> 4;
            int c4 = (idx & 15) << 2;
            float4 v = *(const float4*)(Vb + (size_t)(kTok + rr) * 768 + hOff + c4);
            *(float4*)&KVs[rr * 64 + c4] = v;
        }
        __syncthreads();   // Ps, rowsum, V ready

        {
            float mold = m_s[orow];
            float mnew = fmaxf(mold, rowmax_s[orow]);
            float alpha = __expf(mold - mnew);
            l_r = l_r * alpha + rowsum_s[orow];
            if (op == 0) m_s[orow] = mnew;  // same-warp pair: reads precede write
            #pragma unroll
            for (int j = 0; j < 8; j++) {
                Oc[j].x *= alpha; Oc[j].y *= alpha;
                Oc[j].z *= alpha; Oc[j].w *= alpha;
            }
            #pragma unroll 8
            for (int c = 0; c < 64; c++) {
                float p = Ps[orow * 65 + c];
                #pragma unroll
                for (int j = 0; j < 8; j++) {
                    float4 v = *(const float4*)&KVs[c * 64 + j * 8 + op * 4];
                    Oc[j].x += p * v.x; Oc[j].y += p * v.y;
                    Oc[j].z += p * v.z; Oc[j].w += p * v.w;
                }
            }
        }
        __syncthreads();   // protect m_s / Ps / KVs for next tile
    }

    float inv = 1.f / l_r;
    float* orow_ptr = Ob + (size_t)(qTok + orow) * 768 + hOff;
    #pragma unroll
    for (int j = 0; j < 8; j++) {
        float4 v = Oc[j];
        v.x *= inv; v.y *= inv; v.z *= inv; v.w *= inv;
        *(float4*)(orow_ptr + j * 8 + op * 4) = v;
    }
}

// ---------------------------------------------------------------------------
// Launch sequence
// ---------------------------------------------------------------------------
extern "C" void kernel_launch(void* const* d_in, const int* in_sizes, int n_in,
                              void* d_out, int out_size)
{
    (void)in_sizes; (void)out_size;
    const float* x       = (const float*)d_in[0];
    const float* ln1_g   = (const float*)d_in[1];
    const float* ln1_b   = (const float*)d_in[2];
    const float* ln2_g   = (const float*)d_in[3];
    const float* ln2_b   = (const float*)d_in[4];
    const float* a1_wqkv = (const float*)d_in[5];
    const float* a1_bqkv = (const float*)d_in[6];
    const float* a1_wo   = (const float*)d_in[7];
    const float* a1_bo   = (const float*)d_in[8];
    const float* a2_wqkv = (const float*)d_in[9];
    const float* a2_bqkv = (const float*)d_in[10];
    const float* a2_wo   = (const float*)d_in[11];
    const float* a2_bo   = (const float*)d_in[12];
    const float* fc_w    = (const float*)d_in[13];
    const float* fc_b    = (const float*)d_in[14];
    const float* proj_w  = (const float*)d_in[15];
    const float* proj_b  = (const float*)d_in[16];
    const int*   idxp    = (n_in > 17) ? (const int*)d_in[17] : nullptr;
    float* out = (float*)d_out;

    float *y, *qkv, *o, *x2, *h;
    cudaGetSymbolAddress((void**)&y,  g_y);
    cudaGetSymbolAddress((void**)&qkv, g_qkv);
    cudaGetSymbolAddress((void**)&o,  g_o);
    cudaGetSymbolAddress((void**)&x2, g_x2);
    cudaGetSymbolAddress((void**)&h,  g_h);

    cudaFuncSetAttribute(attn_kernel,
                         cudaFuncAttributeMaxDynamicSharedMemorySize, 50176);

    const size_t SZ = QKV_SZ;
    const int WQ = 589824;     // 768*768

    // 1) y = LN1(x)
    ln_kernel<<<65536, 192>>>(x, ln1_g, ln1_b, y);

    // 2) QKV projections (compact per-view outputs).
    //    module0: Q=y[v0], K=y[v1], V=x[v0,rolled]; module1: Q=y[v1], K=y[v0], V=x[v1,rolled]
    gemm_kernel<<<dim3(6, 256), 256>>>(y, a1_wqkv,          a1_bqkv,        qkv + 0 * SZ, nullptr, 768, 768,  0,  0, -1, 0, idxp);
    gemm_kernel<<<dim3(6, 256), 256>>>(y, a2_wqkv,          a2_bqkv,        qkv + 1 * SZ, nullptr, 768, 768,  1,  0, -1, 0, idxp);
    gemm_kernel<<<dim3(6, 256), 256>>>(y, a1_wqkv + WQ,     a1_bqkv + 768,  qkv + 2 * SZ, nullptr, 768, 768,  1,  0, -1, 0, idxp);
    gemm_kernel<<<dim3(6, 256), 256>>>(y, a2_wqkv + WQ,     a2_bqkv + 768,  qkv + 3 * SZ, nullptr, 768, 768,  0,  0, -1, 0, idxp);
    gemm_kernel<<<dim3(6, 256), 256>>>(x, a1_wqkv + 2 * WQ, a1_bqkv + 1536, qkv + 4 * SZ, nullptr, 768, 768,  0, -1, -1, 0, idxp);
    gemm_kernel<<<dim3(6, 256), 256>>>(x, a2_wqkv + 2 * WQ, a2_bqkv + 1536, qkv + 5 * SZ, nullptr, 768, 768,  1, -1, -1, 0, idxp);

    // 3) windowed flash attention -> g_o
    attn_kernel<<<dim3(8, 12, 128), 128, 50176>>>();

    // 4) out-proj + un-roll + residual: x2 = x + roll^-1(o @ wo.T + bo)
    gemm_kernel<<<dim3(6, 256), 256>>>(o,      a1_wo, a1_bo, x2, x, 768, 768, -2, +1, 0, 0, idxp);
    gemm_kernel<<<dim3(6, 256), 256>>>(o + SZ, a2_wo, a2_bo, x2, x, 768, 768, -2, +1, 1, 0, idxp);

    // 5) y = LN2(x2)
    ln_kernel<<<65536, 192>>>(x2, ln2_g, ln2_b, y);

    // 6) h = gelu(y @ fc_w.T + fc_b)
    gemm_kernel<<<dim3(24, 512), 256>>>(y, fc_w, fc_b, h, nullptr, 768, 3072, -1, 0, -1, 1, idxp);

    // 7) out = x2 + h @ proj_w.T + proj_b
    gemm_kernel<<<dim3(6, 512), 256>>>(h, proj_w, proj_b, out, x2, 3072, 768, -1, 0, -1, 0, idxp);
}

// round 12
// speedup vs baseline: 2.4221x; 2.4221x over previous
#include <cuda_runtime.h>
#include <cstdint>

// ---------------------------------------------------------------------------
// Problem constants: x [B=4, V=2, L=8192, D=768], H=12 heads, hd=64, W=512.
// NOTE: this bench lowers PTX at .target sm_103 (no 'a' suffix) — tcgen05 /
// TMEM are NOT available. Tensor cores are reached via mma.sync (sm_80+ PTX).
// ---------------------------------------------------------------------------
#define DMODEL 768
#define NROWS_TOTAL 65536
#define QKV_SZ 25165824ull      // 32768 * 768

__device__ float g_y [(size_t)NROWS_TOTAL * DMODEL];
__device__ float g_qkv[6 * QKV_SZ];
__device__ float g_o  [2 * QKV_SZ];
__device__ float g_x2 [(size_t)NROWS_TOTAL * DMODEL];
__device__ float g_h  [(size_t)NROWS_TOTAL * 3072];

__device__ __forceinline__ size_t rowOff(int m, int view, int roll) {
    if (view == -1) return (size_t)m;
    if (view == -2) return (size_t)((m & ~8191) | ((m + roll) & 8191));
    int b = m >> 13;
    int l = (m + roll) & 8191;
    return (size_t)((((b << 1) + view) << 13) + l);
}

// ------------------------- PTX helpers (plain sm_103) ----------------------
__device__ __forceinline__ uint32_t smem_u32(const void* p) {
    uint32_t a;
    asm("{ .reg .u64 t; cvta.to.shared.u64 t, %1; cvt.u32.u64 %0, t; }"
        : "=r"(a) : "l"(p));
    return a;
}
__device__ __forceinline__ void cp_async16(uint32_t s, const float* g) {
    asm volatile("cp.async.cg.shared.global [%0], [%1], 16;\n"
                 :: "r"(s), "l"(__cvta_generic_to_global(g)) : "memory");
}
#define CP_COMMIT() asm volatile("cp.async.commit_group;\n" ::: "memory")
#define CP_WAIT(n)  asm volatile("cp.async.wait_group %0;\n" :: "n"(n) : "memory")

__device__ __forceinline__ uint32_t f2tf(float f) {
    uint32_t u;
    asm("cvt.rna.tf32.f32 %0, %1;" : "=r"(u) : "f"(f));
    return u;
}
__device__ __forceinline__ void mma_tf32(float* c, const uint32_t* a, const uint32_t* b) {
    asm volatile(
        "mma.sync.aligned.m16n8k8.row.col.f32.tf32.tf32.f32 "
        "{%0,%1,%2,%3}, {%4,%5,%6,%7}, {%8,%9}, {%0,%1,%2,%3};"
        : "+f"(c[0]), "+f"(c[1]), "+f"(c[2]), "+f"(c[3])
        : "r"(a[0]), "r"(a[1]), "r"(a[2]), "r"(a[3]), "r"(b[0]), "r"(b[1]));
}

// ---------------------------------------------------------------------------
// tf32 mma.sync GEMM: C[m,n] = sum_k A[m,k]*W[n,k] (+bias, gelu, resid)
// 128x128 block tile, 256 thr (8 warps, 2x4), warp tile 64x32 (4x4 m16n8k8).
// K chunks of 32 floats, cp.async double buffer. Smem LDA=36 floats:
// fragment loads land on banks (4g+q) mod 32 — conflict-free.
// ---------------------------------------------------------------------------
__global__ void __launch_bounds__(256)
tgemm_kernel(const float* __restrict__ A, const float* __restrict__ W,
             const float* __restrict__ bias, float* __restrict__ C,
             const float* __restrict__ resid,
             int K, int N, int Aview, int ArollSign, int Cview, int actGelu,
             const int* __restrict__ idxp)
{
    extern __shared__ __align__(16) float smemf[];   // 2 bufs * (A 128*36 + B 128*36)
    uint32_t sb = smem_u32(smemf);

    int tid  = threadIdx.x;
    int wid  = tid >> 5;
    int lane = tid & 31;
    int bn = blockIdx.x, bm = blockIdx.y;

    int shf = idxp ? ((idxp[0] & 1) << 8) : 0;   // W/2 = 256 if index odd
    int roll = 0;
    if (ArollSign > 0) roll = shf;
    else if (ArollSign < 0) roll = (8192 - shf) & 8191;

    // cp.async mapping: thread -> rows r0+32i (i=0..3), k-quad kq (16B)
    int r0 = tid >> 3;          // 0..31
    int kq = tid & 7;           // 0..7  (16B chunk within 32-float K-slab)
    const float* aptr[4];
    const float* bptr[4];
    #pragma unroll
    for (int i = 0; i < 4; i++) {
        int row = r0 + 32 * i;
        aptr[i] = A + rowOff(bm * 128 + row, Aview, roll) * (size_t)K + (kq << 2);
        bptr[i] = W + (size_t)(bn * 128 + row) * K + (kq << 2);
    }
    uint32_t dstA = (uint32_t)(r0 * 144 + kq * 16);   // LDA = 36 floats = 144 B

    auto fill = [&](int b, int kt) {
        uint32_t base = sb + (uint32_t)b * 36864u;    // bytes per buffer
        int ko = kt << 5;
        #pragma unroll
        for (int i = 0; i < 4; i++) {
            cp_async16(base + dstA + (uint32_t)(i * 4608),           aptr[i] + ko);
            cp_async16(base + 18432u + dstA + (uint32_t)(i * 4608),  bptr[i] + ko);
        }
    };

    // warp layout: 2 (M) x 4 (N); warp tile 64x32
    int warpM = wid & 1, warpN = wid >> 1;
    int m_base = warpM * 64, n_base = warpN * 32;
    int g = lane >> 2, q = lane & 3;

    float acc[4][4][4];
    #pragma unroll
    for (int tm = 0; tm < 4; tm++)
        #pragma unroll
        for (int tn = 0; tn < 4; tn++)
            #pragma unroll
            for (int e = 0; e < 4; e++) acc[tm][tn][e] = 0.f;

    int KT = K >> 5;
    fill(0, 0); CP_COMMIT();
    fill(1, 1); CP_COMMIT();

    for (int kt = 0; kt < KT; kt++) {
        int b = kt & 1;
        if (kt == KT - 1) CP_WAIT(0); else CP_WAIT(1);
        __syncthreads();

        const float* Ab = smemf + b * 9216;
        const float* Bb = Ab + 4608;

        #pragma unroll
        for (int kk = 0; kk < 32; kk += 8) {
            uint32_t af[4][4], bf[4][2];
            #pragma unroll
            for (int tm = 0; tm < 4; tm++) {
                int r = m_base + tm * 16 + g;
                af[tm][0] = f2tf(Ab[r * 36 + kk + q]);
                af[tm][1] = f2tf(Ab[(r + 8) * 36 + kk + q]);
                af[tm][2] = f2tf(Ab[r * 36 + kk + 4 + q]);
                af[tm][3] = f2tf(Ab[(r + 8) * 36 + kk + 4 + q]);
            }
            #pragma unroll
            for (int tn = 0; tn < 4; tn++) {
                int c = n_base + tn * 8 + g;
                bf[tn][0] = f2tf(Bb[c * 36 + kk + q]);
                bf[tn][1] = f2tf(Bb[c * 36 + kk + 4 + q]);
            }
            #pragma unroll
            for (int tm = 0; tm < 4; tm++)
                #pragma unroll
                for (int tn = 0; tn < 4; tn++)
                    mma_tf32(acc[tm][tn], af[tm], bf[tn]);
        }
        __syncthreads();
        if (kt + 2 < KT) { fill(b, kt + 2); CP_COMMIT(); }
    }

    // Epilogue: c0,c1 -> (row g, col 2q,2q+1); c2,c3 -> (row g+8, same cols)
    #pragma unroll
    for (int tm = 0; tm < 4; tm++) {
        int mr = bm * 128 + m_base + tm * 16 + g;
        size_t cb0 = rowOff(mr,     Cview, 0) * (size_t)N;
        size_t cb1 = rowOff(mr + 8, Cview, 0) * (size_t)N;
        #pragma unroll
        for (int tn = 0; tn < 4; tn++) {
            int col = bn * 128 + n_base + tn * 8 + 2 * q;
            float2 bv = *(const float2*)(bias + col);
            float2 v0, v1;
            v0.x = acc[tm][tn][0] + bv.x;  v0.y = acc[tm][tn][1] + bv.y;
            v1.x = acc[tm][tn][2] + bv.x;  v1.y = acc[tm][tn][3] + bv.y;
            if (actGelu) {
                v0.x = v0.x / (1.f + __expf(-1.702f * v0.x));
                v0.y = v0.y / (1.f + __expf(-1.702f * v0.y));
                v1.x = v1.x / (1.f + __expf(-1.702f * v1.x));
                v1.y = v1.y / (1.f + __expf(-1.702f * v1.y));
            }
            if (resid) {
                float2 r0v = *(const float2*)(resid + cb0 + col);
                float2 r1v = *(const float2*)(resid + cb1 + col);
                v0.x += r0v.x; v0.y += r0v.y;
                v1.x += r1v.x; v1.y += r1v.y;
            }
            *(float2*)(C + cb0 + col) = v0;
            *(float2*)(C + cb1 + col) = v1;
        }
    }
}

// ---------------------------------------------------------------------------
// LayerNorm (unchanged, R1-verified)
// ---------------------------------------------------------------------------
__global__ void __launch_bounds__(192)
ln_kernel(const float* __restrict__ x, const float* __restrict__ g,
          const float* __restrict__ b, float* __restrict__ y)
{
    __shared__ float sh[8];
    int row = blockIdx.x;
    int t = threadIdx.x;
    const float4* xr = (const float4*)(x + (size_t)row * DMODEL);
    float4 v = xr[t];

    float s = v.x + v.y + v.z + v.w;
    #pragma unroll
    for (int o = 16; o; o >>= 1) s += __shfl_xor_sync(0xffffffffu, s, o);
    if ((t & 31) == 0) sh[t >> 5] = s;
    __syncthreads();
    s = sh[0] + sh[1] + sh[2] + sh[3] + sh[4] + sh[5];
    float mean = s * (1.0f / 768.0f);

    float dx = v.x - mean, dy = v.y - mean, dz = v.z - mean, dw = v.w - mean;
    float q = dx * dx + dy * dy + dz * dz + dw * dw;
    __syncthreads();
    #pragma unroll
    for (int o = 16; o; o >>= 1) q += __shfl_xor_sync(0xffffffffu, q, o);
    if ((t & 31) == 0) sh[t >> 5] = q;
    __syncthreads();
    q = sh[0] + sh[1] + sh[2] + sh[3] + sh[4] + sh[5];
    float rs = rsqrtf(q * (1.0f / 768.0f) + 1e-5f);

    float4 gg = ((const float4*)g)[t];
    float4 bb = ((const float4*)b)[t];
    float4 o4;
    o4.x = dx * rs * gg.x + bb.x;
    o4.y = dy * rs * gg.y + bb.y;
    o4.z = dz * rs * gg.z + bb.z;
    o4.w = dw * rs * gg.w + bb.w;
    ((float4*)(y + (size_t)row * DMODEL))[t] = o4;
}

// ---------------------------------------------------------------------------
// Flash attention (SIMT, unchanged, R1-verified)
// ---------------------------------------------------------------------------
__global__ void __launch_bounds__(128)
attn_kernel()
{
    extern __shared__ __align__(16) float smx[];
    float* Qs  = smx;
    float* KVs = Qs + 4096;
    float* Ps  = KVs + 4096;
    float* rowmax_s = Ps + 4160;
    float* rowsum_s = rowmax_s + 64;
    float* m_s      = rowsum_s + 64;

    int t  = threadIdx.x;
    int qt = blockIdx.x;
    int hd = blockIdx.y;
    int z  = blockIdx.z;
    int mod = z >> 6;
    int b   = (z >> 4) & 3;
    int w   = z & 15;

    const float* Qb = g_qkv + (size_t)(0 + mod) * QKV_SZ;
    const float* Kb = g_qkv + (size_t)(2 + mod) * QKV_SZ;
    const float* Vb = g_qkv + (size_t)(4 + mod) * QKV_SZ;
    float* Ob = g_o + (size_t)mod * QKV_SZ;

    int winTok = b * 8192 + w * 512;
    int qTok = winTok + qt * 64;
    int hOff = hd * 64;

    for (int idx = t; idx < 1024; idx += 128) {
        int rr = idx >> 4;
        int c4 = (idx & 15) << 2;
        float4 v = *(const float4*)(Qb + (size_t)(qTok + rr) * 768 + hOff + c4);
        Qs[(c4 + 0) * 64 + rr] = v.x * 0.125f;
        Qs[(c4 + 1) * 64 + rr] = v.y * 0.125f;
        Qs[(c4 + 2) * 64 + rr] = v.z * 0.125f;
        Qs[(c4 + 3) * 64 + rr] = v.w * 0.125f;
    }
    if (t < 64) m_s[t] = -1e30f;

    float4 Oc[8];
    #pragma unroll
    for (int j = 0; j < 8; j++) Oc[j] = make_float4(0.f, 0.f, 0.f, 0.f);
    float l_r = 0.f;

    int r0 = (t >> 3) << 2;
    int c0 = (t & 7) << 3;
    int orow = t >> 1;
    int op = t & 1;

    __syncthreads();

    for (int kt = 0; kt < 8; kt++) {
        int kTok = winTok + kt * 64;
        for (int idx = t; idx < 1024; idx += 128) {
            int rr = idx >> 4;
            int c4 = (idx & 15) << 2;
            float4 v = *(const float4*)(Kb + (size_t)(kTok + rr) * 768 + hOff + c4);
            KVs[(c4 + 0) * 64 + rr] = v.x;
            KVs[(c4 + 1) * 64 + rr] = v.y;
            KVs[(c4 + 2) * 64 + rr] = v.z;
            KVs[(c4 + 3) * 64 + rr] = v.w;
        }
        __syncthreads();

        float S[4][8];
        #pragma unroll
        for (int i = 0; i < 4; i++)
            #pragma unroll
            for (int j = 0; j < 8; j++) S[i][j] = 0.f;

        #pragma unroll 16
        for (int k = 0; k < 64; k++) {
            float4 qv = *(const float4*)&Qs[k * 64 + r0];
            float4 k0 = *(const float4*)&KVs[k * 64 + c0];
            float4 k1 = *(const float4*)&KVs[k * 64 + c0 + 4];
            float qq[4] = {qv.x, qv.y, qv.z, qv.w};
            float kk[8] = {k0.x, k0.y, k0.z, k0.w, k1.x, k1.y, k1.z, k1.w};
            #pragma unroll
            for (int i = 0; i < 4; i++)
                #pragma unroll
                for (int j = 0; j < 8; j++)
                    S[i][j] += qq[i] * kk[j];
        }

        #pragma unroll
        for (int i = 0; i < 4; i++) {
            float rm = S[i][0];
            #pragma unroll
            for (int j = 1; j < 8; j++) rm = fmaxf(rm, S[i][j]);
            rm = fmaxf(rm, __shfl_xor_sync(0xffffffffu, rm, 1));
            rm = fmaxf(rm, __shfl_xor_sync(0xffffffffu, rm, 2));
            rm = fmaxf(rm, __shfl_xor_sync(0xffffffffu, rm, 4));
            if ((t & 7) == 0) rowmax_s[r0 + i] = rm;
        }
        __syncthreads();

        #pragma unroll
        for (int i = 0; i < 4; i++) {
            float mnew = fmaxf(m_s[r0 + i], rowmax_s[r0 + i]);
            float rs = 0.f;
            #pragma unroll
            for (int j = 0; j < 8; j++) {
                float p = __expf(S[i][j] - mnew);
                Ps[(r0 + i) * 65 + c0 + j] = p;
                rs += p;
            }
            rs += __shfl_xor_sync(0xffffffffu, rs, 1);
            rs += __shfl_xor_sync(0xffffffffu, rs, 2);
            rs += __shfl_xor_sync(0xffffffffu, rs, 4);
            if ((t & 7) == 0) rowsum_s[r0 + i] = rs;
        }
        for (int idx = t; idx < 1024; idx += 128) {
            int rr = idx >> 4;
            int c4 = (idx & 15) << 2;
            float4 v = *(const float4*)(Vb + (size_t)(kTok + rr) * 768 + hOff + c4);
            *(float4*)&KVs[rr * 64 + c4] = v;
        }
        __syncthreads();

        {
            float mold = m_s[orow];
            float mnew = fmaxf(mold, rowmax_s[orow]);
            float alpha = __expf(mold - mnew);
            l_r = l_r * alpha + rowsum_s[orow];
            if (op == 0) m_s[orow] = mnew;
            #pragma unroll
            for (int j = 0; j < 8; j++) {
                Oc[j].x *= alpha; Oc[j].y *= alpha;
                Oc[j].z *= alpha; Oc[j].w *= alpha;
            }
            #pragma unroll 8
            for (int c = 0; c < 64; c++) {
                float p = Ps[orow * 65 + c];
                #pragma unroll
                for (int j = 0; j < 8; j++) {
                    float4 v = *(const float4*)&KVs[c * 64 + j * 8 + op * 4];
                    Oc[j].x += p * v.x; Oc[j].y += p * v.y;
                    Oc[j].z += p * v.z; Oc[j].w += p * v.w;
                }
            }
        }
        __syncthreads();
    }

    float inv = 1.f / l_r;
    float* orow_ptr = Ob + (size_t)(qTok + orow) * 768 + hOff;
    #pragma unroll
    for (int j = 0; j < 8; j++) {
        float4 v = Oc[j];
        v.x *= inv; v.y *= inv; v.z *= inv; v.w *= inv;
        *(float4*)(orow_ptr + j * 8 + op * 4) = v;
    }
}

// ---------------------------------------------------------------------------
// Launch sequence
// ---------------------------------------------------------------------------
extern "C" void kernel_launch(void* const* d_in, const int* in_sizes, int n_in,
                              void* d_out, int out_size)
{
    (void)in_sizes; (void)out_size;
    const float* x       = (const float*)d_in[0];
    const float* ln1_g   = (const float*)d_in[1];
    const float* ln1_b   = (const float*)d_in[2];
    const float* ln2_g   = (const float*)d_in[3];
    const float* ln2_b   = (const float*)d_in[4];
    const float* a1_wqkv = (const float*)d_in[5];
    const float* a1_bqkv = (const float*)d_in[6];
    const float* a1_wo   = (const float*)d_in[7];
    const float* a1_bo   = (const float*)d_in[8];
    const float* a2_wqkv = (const float*)d_in[9];
    const float* a2_bqkv = (const float*)d_in[10];
    const float* a2_wo   = (const float*)d_in[11];
    const float* a2_bo   = (const float*)d_in[12];
    const float* fc_w    = (const float*)d_in[13];
    const float* fc_b    = (const float*)d_in[14];
    const float* proj_w  = (const float*)d_in[15];
    const float* proj_b  = (const float*)d_in[16];
    const int*   idxp    = (n_in > 17) ? (const int*)d_in[17] : nullptr;
    float* out = (float*)d_out;

    float *y, *qkv, *o, *x2, *h;
    cudaGetSymbolAddress((void**)&y,  g_y);
    cudaGetSymbolAddress((void**)&qkv, g_qkv);
    cudaGetSymbolAddress((void**)&o,  g_o);
    cudaGetSymbolAddress((void**)&x2, g_x2);
    cudaGetSymbolAddress((void**)&h,  g_h);

    cudaFuncSetAttribute(attn_kernel,
                         cudaFuncAttributeMaxDynamicSharedMemorySize, 50176);
    cudaFuncSetAttribute(tgemm_kernel,
                         cudaFuncAttributeMaxDynamicSharedMemorySize, 73728);

    const size_t SZ = QKV_SZ;
    const int WQ = 589824;     // 768*768
    const int GS = 73728;      // 2 bufs * (A 128*36 + B 128*36) * 4B

    // 1) y = LN1(x)
    ln_kernel<<<65536, 192>>>(x, ln1_g, ln1_b, y);

    // 2) QKV projections (compact per-view outputs)
    tgemm_kernel<<<dim3(6, 256), 256, GS>>>(y, a1_wqkv,          a1_bqkv,        qkv + 0 * SZ, nullptr, 768, 768,  0,  0, -1, 0, idxp);
    tgemm_kernel<<<dim3(6, 256), 256, GS>>>(y, a2_wqkv,          a2_bqkv,        qkv + 1 * SZ, nullptr, 768, 768,  1,  0, -1, 0, idxp);
    tgemm_kernel<<<dim3(6, 256), 256, GS>>>(y, a1_wqkv + WQ,     a1_bqkv + 768,  qkv + 2 * SZ, nullptr, 768, 768,  1,  0, -1, 0, idxp);
    tgemm_kernel<<<dim3(6, 256), 256, GS>>>(y, a2_wqkv + WQ,     a2_bqkv + 768,  qkv + 3 * SZ, nullptr, 768, 768,  0,  0, -1, 0, idxp);
    tgemm_kernel<<<dim3(6, 256), 256, GS>>>(x, a1_wqkv + 2 * WQ, a1_bqkv + 1536, qkv + 4 * SZ, nullptr, 768, 768,  0, -1, -1, 0, idxp);
    tgemm_kernel<<<dim3(6, 256), 256, GS>>>(x, a2_wqkv + 2 * WQ, a2_bqkv + 1536, qkv + 5 * SZ, nullptr, 768, 768,  1, -1, -1, 0, idxp);

    // 3) windowed flash attention
    attn_kernel<<<dim3(8, 12, 128), 128, 50176>>>();

    // 4) out-proj + un-roll + residual
    tgemm_kernel<<<dim3(6, 256), 256, GS>>>(o,      a1_wo, a1_bo, x2, x, 768, 768, -2, +1, 0, 0, idxp);
    tgemm_kernel<<<dim3(6, 256), 256, GS>>>(o + SZ, a2_wo, a2_bo, x2, x, 768, 768, -2, +1, 1, 0, idxp);

    // 5) y = LN2(x2)
    ln_kernel<<<65536, 192>>>(x2, ln2_g, ln2_b, y);

    // 6) h = gelu(y @ fc_w.T + fc_b)
    tgemm_kernel<<<dim3(24, 512), 256, GS>>>(y, fc_w, fc_b, h, nullptr, 768, 3072, -1, 0, -1, 1, idxp);

    // 7) out = x2 + h @ proj_w.T + proj_b
    tgemm_kernel<<<dim3(6, 512), 256, GS>>>(h, proj_w, proj_b, out, x2, 3072, 768, -1, 0, -1, 0, idxp);
}

// round 13
// speedup vs baseline: 3.2704x; 1.3502x over previous
#include <cuda_runtime.h>
#include <cstdint>

// ---------------------------------------------------------------------------
// Problem constants: x [B=4, V=2, L=8192, D=768], H=12 heads, hd=64, W=512.
// Bench lowers PTX at .target sm_103 (no 'a') — tcgen05/TMEM unavailable.
// Tensor cores via mma.sync m16n8k8 tf32 (verified in R12).
// ---------------------------------------------------------------------------
#define DMODEL 768
#define NROWS_TOTAL 65536
#define QKV_SZ 25165824ull      // 32768 * 768

__device__ float g_y [(size_t)NROWS_TOTAL * DMODEL];
__device__ float g_qkv[6 * QKV_SZ];
__device__ float g_o  [2 * QKV_SZ];
__device__ float g_x2 [(size_t)NROWS_TOTAL * DMODEL];
__device__ float g_h  [(size_t)NROWS_TOTAL * 3072];

__device__ __forceinline__ size_t rowOff(int m, int view, int roll) {
    if (view == -1) return (size_t)m;
    if (view == -2) return (size_t)((m & ~8191) | ((m + roll) & 8191));
    int b = m >> 13;
    int l = (m + roll) & 8191;
    return (size_t)((((b << 1) + view) << 13) + l);
}

// ------------------------- PTX helpers -------------------------------------
__device__ __forceinline__ uint32_t smem_u32(const void* p) {
    uint32_t a;
    asm("{ .reg .u64 t; cvta.to.shared.u64 t, %1; cvt.u32.u64 %0, t; }"
        : "=r"(a) : "l"(p));
    return a;
}
__device__ __forceinline__ void cp_async16(uint32_t s, const float* g) {
    asm volatile("cp.async.cg.shared.global [%0], [%1], 16;\n"
                 :: "r"(s), "l"(__cvta_generic_to_global(g)) : "memory");
}
#define CP_COMMIT() asm volatile("cp.async.commit_group;\n" ::: "memory")
#define CP_WAIT(n)  asm volatile("cp.async.wait_group %0;\n" :: "n"(n) : "memory")

__device__ __forceinline__ uint32_t f2tf(float f) {
    uint32_t u;
    asm("cvt.rna.tf32.f32 %0, %1;" : "=r"(u) : "f"(f));
    return u;
}
__device__ __forceinline__ void mma_tf32(float* c, const uint32_t* a, const uint32_t* b) {
    asm volatile(
        "mma.sync.aligned.m16n8k8.row.col.f32.tf32.tf32.f32 "
        "{%0,%1,%2,%3}, {%4,%5,%6,%7}, {%8,%9}, {%0,%1,%2,%3};"
        : "+f"(c[0]), "+f"(c[1]), "+f"(c[2]), "+f"(c[3])
        : "r"(a[0]), "r"(a[1]), "r"(a[2]), "r"(a[3]), "r"(b[0]), "r"(b[1]));
}

// ---------------------------------------------------------------------------
// tf32 mma.sync GEMM (R12-verified): C = A*W^T (+bias, gelu, resid)
// ---------------------------------------------------------------------------
__global__ void __launch_bounds__(256)
tgemm_kernel(const float* __restrict__ A, const float* __restrict__ W,
             const float* __restrict__ bias, float* __restrict__ C,
             const float* __restrict__ resid,
             int K, int N, int Aview, int ArollSign, int Cview, int actGelu,
             const int* __restrict__ idxp)
{
    extern __shared__ __align__(16) float smemf[];
    uint32_t sb = smem_u32(smemf);

    int tid  = threadIdx.x;
    int wid  = tid >> 5;
    int lane = tid & 31;
    int bn = blockIdx.x, bm = blockIdx.y;

    int shf = idxp ? ((idxp[0] & 1) << 8) : 0;
    int roll = 0;
    if (ArollSign > 0) roll = shf;
    else if (ArollSign < 0) roll = (8192 - shf) & 8191;

    int r0 = tid >> 3;
    int kq = tid & 7;
    const float* aptr[4];
    const float* bptr[4];
    #pragma unroll
    for (int i = 0; i < 4; i++) {
        int row = r0 + 32 * i;
        aptr[i] = A + rowOff(bm * 128 + row, Aview, roll) * (size_t)K + (kq << 2);
        bptr[i] = W + (size_t)(bn * 128 + row) * K + (kq << 2);
    }
    uint32_t dstA = (uint32_t)(r0 * 144 + kq * 16);

    auto fill = [&](int b, int kt) {
        uint32_t base = sb + (uint32_t)b * 36864u;
        int ko = kt << 5;
        #pragma unroll
        for (int i = 0; i < 4; i++) {
            cp_async16(base + dstA + (uint32_t)(i * 4608),           aptr[i] + ko);
            cp_async16(base + 18432u + dstA + (uint32_t)(i * 4608),  bptr[i] + ko);
        }
    };

    int warpM = wid & 1, warpN = wid >> 1;
    int m_base = warpM * 64, n_base = warpN * 32;
    int g = lane >> 2, q = lane & 3;

    float acc[4][4][4];
    #pragma unroll
    for (int tm = 0; tm < 4; tm++)
        #pragma unroll
        for (int tn = 0; tn < 4; tn++)
            #pragma unroll
            for (int e = 0; e < 4; e++) acc[tm][tn][e] = 0.f;

    int KT = K >> 5;
    fill(0, 0); CP_COMMIT();
    fill(1, 1); CP_COMMIT();

    for (int kt = 0; kt < KT; kt++) {
        int b = kt & 1;
        if (kt == KT - 1) CP_WAIT(0); else CP_WAIT(1);
        __syncthreads();

        const float* Ab = smemf + b * 9216;
        const float* Bb = Ab + 4608;

        #pragma unroll
        for (int kk = 0; kk < 32; kk += 8) {
            uint32_t af[4][4], bf[4][2];
            #pragma unroll
            for (int tm = 0; tm < 4; tm++) {
                int r = m_base + tm * 16 + g;
                af[tm][0] = f2tf(Ab[r * 36 + kk + q]);
                af[tm][1] = f2tf(Ab[(r + 8) * 36 + kk + q]);
                af[tm][2] = f2tf(Ab[r * 36 + kk + 4 + q]);
                af[tm][3] = f2tf(Ab[(r + 8) * 36 + kk + 4 + q]);
            }
            #pragma unroll
            for (int tn = 0; tn < 4; tn++) {
                int c = n_base + tn * 8 + g;
                bf[tn][0] = f2tf(Bb[c * 36 + kk + q]);
                bf[tn][1] = f2tf(Bb[c * 36 + kk + 4 + q]);
            }
            #pragma unroll
            for (int tm = 0; tm < 4; tm++)
                #pragma unroll
                for (int tn = 0; tn < 4; tn++)
                    mma_tf32(acc[tm][tn], af[tm], bf[tn]);
        }
        __syncthreads();
        if (kt + 2 < KT) { fill(b, kt + 2); CP_COMMIT(); }
    }

    #pragma unroll
    for (int tm = 0; tm < 4; tm++) {
        int mr = bm * 128 + m_base + tm * 16 + g;
        size_t cb0 = rowOff(mr,     Cview, 0) * (size_t)N;
        size_t cb1 = rowOff(mr + 8, Cview, 0) * (size_t)N;
        #pragma unroll
        for (int tn = 0; tn < 4; tn++) {
            int col = bn * 128 + n_base + tn * 8 + 2 * q;
            float2 bv = *(const float2*)(bias + col);
            float2 v0, v1;
            v0.x = acc[tm][tn][0] + bv.x;  v0.y = acc[tm][tn][1] + bv.y;
            v1.x = acc[tm][tn][2] + bv.x;  v1.y = acc[tm][tn][3] + bv.y;
            if (actGelu) {
                v0.x = v0.x / (1.f + __expf(-1.702f * v0.x));
                v0.y = v0.y / (1.f + __expf(-1.702f * v0.y));
                v1.x = v1.x / (1.f + __expf(-1.702f * v1.x));
                v1.y = v1.y / (1.f + __expf(-1.702f * v1.y));
            }
            if (resid) {
                float2 r0v = *(const float2*)(resid + cb0 + col);
                float2 r1v = *(const float2*)(resid + cb1 + col);
                v0.x += r0v.x; v0.y += r0v.y;
                v1.x += r1v.x; v1.y += r1v.y;
            }
            *(float2*)(C + cb0 + col) = v0;
            *(float2*)(C + cb1 + col) = v1;
        }
    }
}

// ---------------------------------------------------------------------------
// LayerNorm (R1-verified)
// ---------------------------------------------------------------------------
__global__ void __launch_bounds__(192)
ln_kernel(const float* __restrict__ x, const float* __restrict__ g,
          const float* __restrict__ b, float* __restrict__ y)
{
    __shared__ float sh[8];
    int row = blockIdx.x;
    int t = threadIdx.x;
    const float4* xr = (const float4*)(x + (size_t)row * DMODEL);
    float4 v = xr[t];

    float s = v.x + v.y + v.z + v.w;
    #pragma unroll
    for (int o = 16; o; o >>= 1) s += __shfl_xor_sync(0xffffffffu, s, o);
    if ((t & 31) == 0) sh[t >> 5] = s;
    __syncthreads();
    s = sh[0] + sh[1] + sh[2] + sh[3] + sh[4] + sh[5];
    float mean = s * (1.0f / 768.0f);

    float dx = v.x - mean, dy = v.y - mean, dz = v.z - mean, dw = v.w - mean;
    float q = dx * dx + dy * dy + dz * dz + dw * dw;
    __syncthreads();
    #pragma unroll
    for (int o = 16; o; o >>= 1) q += __shfl_xor_sync(0xffffffffu, q, o);
    if ((t & 31) == 0) sh[t >> 5] = q;
    __syncthreads();
    q = sh[0] + sh[1] + sh[2] + sh[3] + sh[4] + sh[5];
    float rs = rsqrtf(q * (1.0f / 768.0f) + 1e-5f);

    float4 gg = ((const float4*)g)[t];
    float4 bb = ((const float4*)b)[t];
    float4 o4;
    o4.x = dx * rs * gg.x + bb.x;
    o4.y = dy * rs * gg.y + bb.y;
    o4.z = dz * rs * gg.z + bb.z;
    o4.w = dw * rs * gg.w + bb.w;
    ((float4*)(y + (size_t)row * DMODEL))[t] = o4;
}

// ---------------------------------------------------------------------------
// Flash attention on mma.sync tensor cores.
// Block = (64-row q-tile, head, mod*b*w). 128 threads = 4 warps; warp owns
// 16 q-rows. S = Q*K^T via m16n8k8 (Q row-major [64][68], K tile [key][d] is
// natively col-major k x n). Online softmax in registers (row owned by one
// quad; stats via shfl). P staged to smem; V loaded transposed [d][key] into
// the K buffer; O = P*V via m16n8k8.
// ---------------------------------------------------------------------------
#define ALD 68   // smem leading dim (floats): banks (4g+q) mod 32, conflict-free

__global__ void __launch_bounds__(128)
attn_kernel()
{
    extern __shared__ __align__(16) float smx[];
    float* Qs  = smx;              // [64][ALD]
    float* KVs = Qs + 64 * ALD;    // [64][ALD]: K rows, then V^T [d][key]
    float* Ps  = KVs + 64 * ALD;   // [64][ALD]

    int t  = threadIdx.x;
    int wid = t >> 5, lane = t & 31;
    int g = lane >> 2, q = lane & 3;
    int rbase = wid * 16;          // warp's q-row base within tile

    int qt = blockIdx.x;
    int hd = blockIdx.y;
    int z  = blockIdx.z;
    int mod = z >> 6;
    int b   = (z >> 4) & 3;
    int w   = z & 15;

    const float* Qb = g_qkv + (size_t)(0 + mod) * QKV_SZ;
    const float* Kb = g_qkv + (size_t)(2 + mod) * QKV_SZ;
    const float* Vb = g_qkv + (size_t)(4 + mod) * QKV_SZ;
    float* Ob = g_o + (size_t)mod * QKV_SZ;

    int winTok = b * 8192 + w * 512;
    int qTok = winTok + qt * 64;
    int hOff = hd * 64;

    // Load Q tile row-major, pre-scaled by 1/sqrt(64)
    for (int idx = t; idx < 1024; idx += 128) {
        int rr = idx >> 4;
        int c4 = (idx & 15) << 2;
        float4 v = *(const float4*)(Qb + (size_t)(qTok + rr) * 768 + hOff + c4);
        v.x *= 0.125f; v.y *= 0.125f; v.z *= 0.125f; v.w *= 0.125f;
        *(float4*)&Qs[rr * ALD + c4] = v;
    }

    float Oa[8][4];
    #pragma unroll
    for (int dt = 0; dt < 8; dt++)
        #pragma unroll
        for (int e = 0; e < 4; e++) Oa[dt][e] = 0.f;
    float m0 = -1e30f, m1 = -1e30f, l0 = 0.f, l1 = 0.f;

    for (int kt = 0; kt < 8; kt++) {
        int kTok = winTok + kt * 64;
        // K tile row-major [key][d]
        for (int idx = t; idx < 1024; idx += 128) {
            int rr = idx >> 4;
            int c4 = (idx & 15) << 2;
            float4 v = *(const float4*)(Kb + (size_t)(kTok + rr) * 768 + hOff + c4);
            *(float4*)&KVs[rr * ALD + c4] = v;
        }
        __syncthreads();   // Q (first iter) + K visible

        // S = Q*K^T : A rows rbase+g/g+8, B cols = keys
        float S[8][4];
        #pragma unroll
        for (int nt = 0; nt < 8; nt++)
            #pragma unroll
            for (int e = 0; e < 4; e++) S[nt][e] = 0.f;

        #pragma unroll
        for (int kk = 0; kk < 64; kk += 8) {
            uint32_t af[4];
            af[0] = f2tf(Qs[(rbase + g) * ALD + kk + q]);
            af[1] = f2tf(Qs[(rbase + g + 8) * ALD + kk + q]);
            af[2] = f2tf(Qs[(rbase + g) * ALD + kk + 4 + q]);
            af[3] = f2tf(Qs[(rbase + g + 8) * ALD + kk + 4 + q]);
            #pragma unroll
            for (int nt = 0; nt < 8; nt++) {
                uint32_t bf[2];
                bf[0] = f2tf(KVs[(nt * 8 + g) * ALD + kk + q]);
                bf[1] = f2tf(KVs[(nt * 8 + g) * ALD + kk + 4 + q]);
                mma_tf32(S[nt], af, bf);
            }
        }
        __syncthreads();   // all warps done reading K; KVs free for V

        // Online softmax (rows rbase+g and rbase+g+8; quad = lanes sharing g)
        float mx0 = -1e30f, mx1 = -1e30f;
        #pragma unroll
        for (int nt = 0; nt < 8; nt++) {
            mx0 = fmaxf(mx0, fmaxf(S[nt][0], S[nt][1]));
            mx1 = fmaxf(mx1, fmaxf(S[nt][2], S[nt][3]));
        }
        mx0 = fmaxf(mx0, __shfl_xor_sync(0xffffffffu, mx0, 1));
        mx0 = fmaxf(mx0, __shfl_xor_sync(0xffffffffu, mx0, 2));
        mx1 = fmaxf(mx1, __shfl_xor_sync(0xffffffffu, mx1, 1));
        mx1 = fmaxf(mx1, __shfl_xor_sync(0xffffffffu, mx1, 2));

        float mn0 = fmaxf(m0, mx0), mn1 = fmaxf(m1, mx1);
        float al0 = __expf(m0 - mn0), al1 = __expf(m1 - mn1);
        float sum0 = 0.f, sum1 = 0.f;
        #pragma unroll
        for (int nt = 0; nt < 8; nt++) {
            float p00 = __expf(S[nt][0] - mn0);
            float p01 = __expf(S[nt][1] - mn0);
            float p10 = __expf(S[nt][2] - mn1);
            float p11 = __expf(S[nt][3] - mn1);
            sum0 += p00 + p01;
            sum1 += p10 + p11;
            float2 w0 = make_float2(p00, p01);
            float2 w1 = make_float2(p10, p11);
            *(float2*)&Ps[(rbase + g) * ALD + nt * 8 + 2 * q] = w0;
            *(float2*)&Ps[(rbase + g + 8) * ALD + nt * 8 + 2 * q] = w1;
        }
        sum0 += __shfl_xor_sync(0xffffffffu, sum0, 1);
        sum0 += __shfl_xor_sync(0xffffffffu, sum0, 2);
        sum1 += __shfl_xor_sync(0xffffffffu, sum1, 1);
        sum1 += __shfl_xor_sync(0xffffffffu, sum1, 2);
        l0 = l0 * al0 + sum0;
        l1 = l1 * al1 + sum1;
        m0 = mn0; m1 = mn1;
        #pragma unroll
        for (int dt = 0; dt < 8; dt++) {
            Oa[dt][0] *= al0; Oa[dt][1] *= al0;
            Oa[dt][2] *= al1; Oa[dt][3] *= al1;
        }

        // Load V transposed: KVs[d][key]
        for (int idx = t; idx < 1024; idx += 128) {
            int key = idx >> 4;
            int d4 = (idx & 15) << 2;
            float4 v = *(const float4*)(Vb + (size_t)(kTok + key) * 768 + hOff + d4);
            KVs[(d4 + 0) * ALD + key] = v.x;
            KVs[(d4 + 1) * ALD + key] = v.y;
            KVs[(d4 + 2) * ALD + key] = v.z;
            KVs[(d4 + 3) * ALD + key] = v.w;
        }
        __syncthreads();   // Ps + V^T visible

        // O += P*V : A = Ps rows (k=key), B = V^T[d][key] (col-major k x n=d)
        #pragma unroll
        for (int kk = 0; kk < 64; kk += 8) {
            uint32_t af[4];
            af[0] = f2tf(Ps[(rbase + g) * ALD + kk + q]);
            af[1] = f2tf(Ps[(rbase + g + 8) * ALD + kk + q]);
            af[2] = f2tf(Ps[(rbase + g) * ALD + kk + 4 + q]);
            af[3] = f2tf(Ps[(rbase + g + 8) * ALD + kk + 4 + q]);
            #pragma unroll
            for (int dt = 0; dt < 8; dt++) {
                uint32_t bf[2];
                bf[0] = f2tf(KVs[(dt * 8 + g) * ALD + kk + q]);
                bf[1] = f2tf(KVs[(dt * 8 + g) * ALD + kk + 4 + q]);
                mma_tf32(Oa[dt], af, bf);
            }
        }
        __syncthreads();   // done with KVs/Ps before next tile overwrites
    }

    float inv0 = 1.f / l0, inv1 = 1.f / l1;
    float* orow0 = Ob + (size_t)(qTok + rbase + g) * 768 + hOff;
    float* orow1 = Ob + (size_t)(qTok + rbase + g + 8) * 768 + hOff;
    #pragma unroll
    for (int dt = 0; dt < 8; dt++) {
        int col = dt * 8 + 2 * q;
        *(float2*)(orow0 + col) = make_float2(Oa[dt][0] * inv0, Oa[dt][1] * inv0);
        *(float2*)(orow1 + col) = make_float2(Oa[dt][2] * inv1, Oa[dt][3] * inv1);
    }
}

// ---------------------------------------------------------------------------
// Launch sequence
// ---------------------------------------------------------------------------
extern "C" void kernel_launch(void* const* d_in, const int* in_sizes, int n_in,
                              void* d_out, int out_size)
{
    (void)in_sizes; (void)out_size;
    const float* x       = (const float*)d_in[0];
    const float* ln1_g   = (const float*)d_in[1];
    const float* ln1_b   = (const float*)d_in[2];
    const float* ln2_g   = (const float*)d_in[3];
    const float* ln2_b   = (const float*)d_in[4];
    const float* a1_wqkv = (const float*)d_in[5];
    const float* a1_bqkv = (const float*)d_in[6];
    const float* a1_wo   = (const float*)d_in[7];
    const float* a1_bo   = (const float*)d_in[8];
    const float* a2_wqkv = (const float*)d_in[9];
    const float* a2_bqkv = (const float*)d_in[10];
    const float* a2_wo   = (const float*)d_in[11];
    const float* a2_bo   = (const float*)d_in[12];
    const float* fc_w    = (const float*)d_in[13];
    const float* fc_b    = (const float*)d_in[14];
    const float* proj_w  = (const float*)d_in[15];
    const float* proj_b  = (const float*)d_in[16];
    const int*   idxp    = (n_in > 17) ? (const int*)d_in[17] : nullptr;
    float* out = (float*)d_out;

    float *y, *qkv, *o, *x2, *h;
    cudaGetSymbolAddress((void**)&y,  g_y);
    cudaGetSymbolAddress((void**)&qkv, g_qkv);
    cudaGetSymbolAddress((void**)&o,  g_o);
    cudaGetSymbolAddress((void**)&x2, g_x2);
    cudaGetSymbolAddress((void**)&h,  g_h);

    const int AS = 3 * 64 * ALD * 4;   // 52224 B
    cudaFuncSetAttribute(attn_kernel,
                         cudaFuncAttributeMaxDynamicSharedMemorySize, AS);
    cudaFuncSetAttribute(tgemm_kernel,
                         cudaFuncAttributeMaxDynamicSharedMemorySize, 73728);

    const size_t SZ = QKV_SZ;
    const int WQ = 589824;     // 768*768
    const int GS = 73728;

    // 1) y = LN1(x)
    ln_kernel<<<65536, 192>>>(x, ln1_g, ln1_b, y);

    // 2) QKV projections (compact per-view outputs)
    tgemm_kernel<<<dim3(6, 256), 256, GS>>>(y, a1_wqkv,          a1_bqkv,        qkv + 0 * SZ, nullptr, 768, 768,  0,  0, -1, 0, idxp);
    tgemm_kernel<<<dim3(6, 256), 256, GS>>>(y, a2_wqkv,          a2_bqkv,        qkv + 1 * SZ, nullptr, 768, 768,  1,  0, -1, 0, idxp);
    tgemm_kernel<<<dim3(6, 256), 256, GS>>>(y, a1_wqkv + WQ,     a1_bqkv + 768,  qkv + 2 * SZ, nullptr, 768, 768,  1,  0, -1, 0, idxp);
    tgemm_kernel<<<dim3(6, 256), 256, GS>>>(y, a2_wqkv + WQ,     a2_bqkv + 768,  qkv + 3 * SZ, nullptr, 768, 768,  0,  0, -1, 0, idxp);
    tgemm_kernel<<<dim3(6, 256), 256, GS>>>(x, a1_wqkv + 2 * WQ, a1_bqkv + 1536, qkv + 4 * SZ, nullptr, 768, 768,  0, -1, -1, 0, idxp);
    tgemm_kernel<<<dim3(6, 256), 256, GS>>>(x, a2_wqkv + 2 * WQ, a2_bqkv + 1536, qkv + 5 * SZ, nullptr, 768, 768,  1, -1, -1, 0, idxp);

    // 3) windowed flash attention (tensor cores)
    attn_kernel<<<dim3(8, 12, 128), 128, AS>>>();

    // 4) out-proj + un-roll + residual
    tgemm_kernel<<<dim3(6, 256), 256, GS>>>(o,      a1_wo, a1_bo, x2, x, 768, 768, -2, +1, 0, 0, idxp);
    tgemm_kernel<<<dim3(6, 256), 256, GS>>>(o + SZ, a2_wo, a2_bo, x2, x, 768, 768, -2, +1, 1, 0, idxp);

    // 5) y = LN2(x2)
    ln_kernel<<<65536, 192>>>(x2, ln2_g, ln2_b, y);

    // 6) h = gelu(y @ fc_w.T + fc_b)
    tgemm_kernel<<<dim3(24, 512), 256, GS>>>(y, fc_w, fc_b, h, nullptr, 768, 3072, -1, 0, -1, 1, idxp);

    // 7) out = x2 + h @ proj_w.T + proj_b
    tgemm_kernel<<<dim3(6, 512), 256, GS>>>(h, proj_w, proj_b, out, x2, 3072, 768, -1, 0, -1, 0, idxp);
}

// round 14
// speedup vs baseline: 3.6108x; 1.1041x over previous
#include <cuda_runtime.h>
#include <cstdint>

// ---------------------------------------------------------------------------
// Problem constants: x [B=4, V=2, L=8192, D=768], H=12 heads, hd=64, W=512.
// Bench lowers PTX at .target sm_103 (no 'a') — tcgen05/TMEM unavailable.
// Tensor cores via mma.sync m16n8k8 tf32 (verified R12/R13).
// R14: feed raw fp32 bits to tf32 mma (RZ truncation, CUTLASS fast path) —
// removes the cvt.rna ALU stream that co-bottlenecked the tensor pipe.
// ---------------------------------------------------------------------------
#define DMODEL 768
#define NROWS_TOTAL 65536
#define QKV_SZ 25165824ull      // 32768 * 768

__device__ float g_y [(size_t)NROWS_TOTAL * DMODEL];
__device__ float g_qkv[6 * QKV_SZ];
__device__ float g_o  [2 * QKV_SZ];
__device__ float g_x2 [(size_t)NROWS_TOTAL * DMODEL];
__device__ float g_h  [(size_t)NROWS_TOTAL * 3072];

__device__ __forceinline__ size_t rowOff(int m, int view, int roll) {
    if (view == -1) return (size_t)m;
    if (view == -2) return (size_t)((m & ~8191) | ((m + roll) & 8191));
    int b = m >> 13;
    int l = (m + roll) & 8191;
    return (size_t)((((b << 1) + view) << 13) + l);
}

// ------------------------- PTX helpers -------------------------------------
__device__ __forceinline__ uint32_t smem_u32(const void* p) {
    uint32_t a;
    asm("{ .reg .u64 t; cvta.to.shared.u64 t, %1; cvt.u32.u64 %0, t; }"
        : "=r"(a) : "l"(p));
    return a;
}
__device__ __forceinline__ void cp_async16(uint32_t s, const float* g) {
    asm volatile("cp.async.cg.shared.global [%0], [%1], 16;\n"
                 :: "r"(s), "l"(__cvta_generic_to_global(g)) : "memory");
}
#define CP_COMMIT() asm volatile("cp.async.commit_group;\n" ::: "memory")
#define CP_WAIT(n)  asm volatile("cp.async.wait_group %0;\n" :: "n"(n) : "memory")

// RZ fast path: tf32 mma reads only the tf32-significant bits of the register.
__device__ __forceinline__ uint32_t f2tf(float f) {
    return __float_as_uint(f);
}
__device__ __forceinline__ void mma_tf32(float* c, const uint32_t* a, const uint32_t* b) {
    asm volatile(
        "mma.sync.aligned.m16n8k8.row.col.f32.tf32.tf32.f32 "
        "{%0,%1,%2,%3}, {%4,%5,%6,%7}, {%8,%9}, {%0,%1,%2,%3};"
        : "+f"(c[0]), "+f"(c[1]), "+f"(c[2]), "+f"(c[3])
        : "r"(a[0]), "r"(a[1]), "r"(a[2]), "r"(a[3]), "r"(b[0]), "r"(b[1]));
}

// ---------------------------------------------------------------------------
// tf32 mma.sync GEMM (R12-verified): C = A*W^T (+bias, gelu, resid)
// ---------------------------------------------------------------------------
__global__ void __launch_bounds__(256)
tgemm_kernel(const float* __restrict__ A, const float* __restrict__ W,
             const float* __restrict__ bias, float* __restrict__ C,
             const float* __restrict__ resid,
             int K, int N, int Aview, int ArollSign, int Cview, int actGelu,
             const int* __restrict__ idxp)
{
    extern __shared__ __align__(16) float smemf[];
    uint32_t sb = smem_u32(smemf);

    int tid  = threadIdx.x;
    int wid  = tid >> 5;
    int lane = tid & 31;
    int bn = blockIdx.x, bm = blockIdx.y;

    int shf = idxp ? ((idxp[0] & 1) << 8) : 0;
    int roll = 0;
    if (ArollSign > 0) roll = shf;
    else if (ArollSign < 0) roll = (8192 - shf) & 8191;

    int r0 = tid >> 3;
    int kq = tid & 7;
    const float* aptr[4];
    const float* bptr[4];
    #pragma unroll
    for (int i = 0; i < 4; i++) {
        int row = r0 + 32 * i;
        aptr[i] = A + rowOff(bm * 128 + row, Aview, roll) * (size_t)K + (kq << 2);
        bptr[i] = W + (size_t)(bn * 128 + row) * K + (kq << 2);
    }
    uint32_t dstA = (uint32_t)(r0 * 144 + kq * 16);

    auto fill = [&](int b, int kt) {
        uint32_t base = sb + (uint32_t)b * 36864u;
        int ko = kt << 5;
        #pragma unroll
        for (int i = 0; i < 4; i++) {
            cp_async16(base + dstA + (uint32_t)(i * 4608),           aptr[i] + ko);
            cp_async16(base + 18432u + dstA + (uint32_t)(i * 4608),  bptr[i] + ko);
        }
    };

    int warpM = wid & 1, warpN = wid >> 1;
    int m_base = warpM * 64, n_base = warpN * 32;
    int g = lane >> 2, q = lane & 3;

    float acc[4][4][4];
    #pragma unroll
    for (int tm = 0; tm < 4; tm++)
        #pragma unroll
        for (int tn = 0; tn < 4; tn++)
            #pragma unroll
            for (int e = 0; e < 4; e++) acc[tm][tn][e] = 0.f;

    int KT = K >> 5;
    fill(0, 0); CP_COMMIT();
    fill(1, 1); CP_COMMIT();

    for (int kt = 0; kt < KT; kt++) {
        int b = kt & 1;
        if (kt == KT - 1) CP_WAIT(0); else CP_WAIT(1);
        __syncthreads();

        const float* Ab = smemf + b * 9216;
        const float* Bb = Ab + 4608;

        #pragma unroll
        for (int kk = 0; kk < 32; kk += 8) {
            uint32_t af[4][4], bf[4][2];
            #pragma unroll
            for (int tm = 0; tm < 4; tm++) {
                int r = m_base + tm * 16 + g;
                af[tm][0] = f2tf(Ab[r * 36 + kk + q]);
                af[tm][1] = f2tf(Ab[(r + 8) * 36 + kk + q]);
                af[tm][2] = f2tf(Ab[r * 36 + kk + 4 + q]);
                af[tm][3] = f2tf(Ab[(r + 8) * 36 + kk + 4 + q]);
            }
            #pragma unroll
            for (int tn = 0; tn < 4; tn++) {
                int c = n_base + tn * 8 + g;
                bf[tn][0] = f2tf(Bb[c * 36 + kk + q]);
                bf[tn][1] = f2tf(Bb[c * 36 + kk + 4 + q]);
            }
            #pragma unroll
            for (int tm = 0; tm < 4; tm++)
                #pragma unroll
                for (int tn = 0; tn < 4; tn++)
                    mma_tf32(acc[tm][tn], af[tm], bf[tn]);
        }
        __syncthreads();
        if (kt + 2 < KT) { fill(b, kt + 2); CP_COMMIT(); }
    }

    #pragma unroll
    for (int tm = 0; tm < 4; tm++) {
        int mr = bm * 128 + m_base + tm * 16 + g;
        size_t cb0 = rowOff(mr,     Cview, 0) * (size_t)N;
        size_t cb1 = rowOff(mr + 8, Cview, 0) * (size_t)N;
        #pragma unroll
        for (int tn = 0; tn < 4; tn++) {
            int col = bn * 128 + n_base + tn * 8 + 2 * q;
            float2 bv = *(const float2*)(bias + col);
            float2 v0, v1;
            v0.x = acc[tm][tn][0] + bv.x;  v0.y = acc[tm][tn][1] + bv.y;
            v1.x = acc[tm][tn][2] + bv.x;  v1.y = acc[tm][tn][3] + bv.y;
            if (actGelu) {
                v0.x = v0.x / (1.f + __expf(-1.702f * v0.x));
                v0.y = v0.y / (1.f + __expf(-1.702f * v0.y));
                v1.x = v1.x / (1.f + __expf(-1.702f * v1.x));
                v1.y = v1.y / (1.f + __expf(-1.702f * v1.y));
            }
            if (resid) {
                float2 r0v = *(const float2*)(resid + cb0 + col);
                float2 r1v = *(const float2*)(resid + cb1 + col);
                v0.x += r0v.x; v0.y += r0v.y;
                v1.x += r1v.x; v1.y += r1v.y;
            }
            *(float2*)(C + cb0 + col) = v0;
            *(float2*)(C + cb1 + col) = v1;
        }
    }
}

// ---------------------------------------------------------------------------
// LayerNorm (R1-verified)
// ---------------------------------------------------------------------------
__global__ void __launch_bounds__(192)
ln_kernel(const float* __restrict__ x, const float* __restrict__ g,
          const float* __restrict__ b, float* __restrict__ y)
{
    __shared__ float sh[8];
    int row = blockIdx.x;
    int t = threadIdx.x;
    const float4* xr = (const float4*)(x + (size_t)row * DMODEL);
    float4 v = xr[t];

    float s = v.x + v.y + v.z + v.w;
    #pragma unroll
    for (int o = 16; o; o >>= 1) s += __shfl_xor_sync(0xffffffffu, s, o);
    if ((t & 31) == 0) sh[t >> 5] = s;
    __syncthreads();
    s = sh[0] + sh[1] + sh[2] + sh[3] + sh[4] + sh[5];
    float mean = s * (1.0f / 768.0f);

    float dx = v.x - mean, dy = v.y - mean, dz = v.z - mean, dw = v.w - mean;
    float q = dx * dx + dy * dy + dz * dz + dw * dw;
    __syncthreads();
    #pragma unroll
    for (int o = 16; o; o >>= 1) q += __shfl_xor_sync(0xffffffffu, q, o);
    if ((t & 31) == 0) sh[t >> 5] = q;
    __syncthreads();
    q = sh[0] + sh[1] + sh[2] + sh[3] + sh[4] + sh[5];
    float rs = rsqrtf(q * (1.0f / 768.0f) + 1e-5f);

    float4 gg = ((const float4*)g)[t];
    float4 bb = ((const float4*)b)[t];
    float4 o4;
    o4.x = dx * rs * gg.x + bb.x;
    o4.y = dy * rs * gg.y + bb.y;
    o4.z = dz * rs * gg.z + bb.z;
    o4.w = dw * rs * gg.w + bb.w;
    ((float4*)(y + (size_t)row * DMODEL))[t] = o4;
}

// ---------------------------------------------------------------------------
// Flash attention on mma.sync tensor cores (R13-verified structure).
// ---------------------------------------------------------------------------
#define ALD 68   // smem leading dim (floats): banks (4g+q) mod 32, conflict-free

__global__ void __launch_bounds__(128)
attn_kernel()
{
    extern __shared__ __align__(16) float smx[];
    float* Qs  = smx;              // [64][ALD]
    float* KVs = Qs + 64 * ALD;    // [64][ALD]: K rows, then V^T [d][key]
    float* Ps  = KVs + 64 * ALD;   // [64][ALD]

    int t  = threadIdx.x;
    int wid = t >> 5, lane = t & 31;
    int g = lane >> 2, q = lane & 3;
    int rbase = wid * 16;

    int qt = blockIdx.x;
    int hd = blockIdx.y;
    int z  = blockIdx.z;
    int mod = z >> 6;
    int b   = (z >> 4) & 3;
    int w   = z & 15;

    const float* Qb = g_qkv + (size_t)(0 + mod) * QKV_SZ;
    const float* Kb = g_qkv + (size_t)(2 + mod) * QKV_SZ;
    const float* Vb = g_qkv + (size_t)(4 + mod) * QKV_SZ;
    float* Ob = g_o + (size_t)mod * QKV_SZ;

    int winTok = b * 8192 + w * 512;
    int qTok = winTok + qt * 64;
    int hOff = hd * 64;

    for (int idx = t; idx < 1024; idx += 128) {
        int rr = idx >> 4;
        int c4 = (idx & 15) << 2;
        float4 v = *(const float4*)(Qb + (size_t)(qTok + rr) * 768 + hOff + c4);
        v.x *= 0.125f; v.y *= 0.125f; v.z *= 0.125f; v.w *= 0.125f;
        *(float4*)&Qs[rr * ALD + c4] = v;
    }

    float Oa[8][4];
    #pragma unroll
    for (int dt = 0; dt < 8; dt++)
        #pragma unroll
        for (int e = 0; e < 4; e++) Oa[dt][e] = 0.f;
    float m0 = -1e30f, m1 = -1e30f, l0 = 0.f, l1 = 0.f;

    for (int kt = 0; kt < 8; kt++) {
        int kTok = winTok + kt * 64;
        for (int idx = t; idx < 1024; idx += 128) {
            int rr = idx >> 4;
            int c4 = (idx & 15) << 2;
            float4 v = *(const float4*)(Kb + (size_t)(kTok + rr) * 768 + hOff + c4);
            *(float4*)&KVs[rr * ALD + c4] = v;
        }
        __syncthreads();

        float S[8][4];
        #pragma unroll
        for (int nt = 0; nt < 8; nt++)
            #pragma unroll
            for (int e = 0; e < 4; e++) S[nt][e] = 0.f;

        #pragma unroll
        for (int kk = 0; kk < 64; kk += 8) {
            uint32_t af[4];
            af[0] = f2tf(Qs[(rbase + g) * ALD + kk + q]);
            af[1] = f2tf(Qs[(rbase + g + 8) * ALD + kk + q]);
            af[2] = f2tf(Qs[(rbase + g) * ALD + kk + 4 + q]);
            af[3] = f2tf(Qs[(rbase + g + 8) * ALD + kk + 4 + q]);
            #pragma unroll
            for (int nt = 0; nt < 8; nt++) {
                uint32_t bf[2];
                bf[0] = f2tf(KVs[(nt * 8 + g) * ALD + kk + q]);
                bf[1] = f2tf(KVs[(nt * 8 + g) * ALD + kk + 4 + q]);
                mma_tf32(S[nt], af, bf);
            }
        }
        __syncthreads();

        float mx0 = -1e30f, mx1 = -1e30f;
        #pragma unroll
        for (int nt = 0; nt < 8; nt++) {
            mx0 = fmaxf(mx0, fmaxf(S[nt][0], S[nt][1]));
            mx1 = fmaxf(mx1, fmaxf(S[nt][2], S[nt][3]));
        }
        mx0 = fmaxf(mx0, __shfl_xor_sync(0xffffffffu, mx0, 1));
        mx0 = fmaxf(mx0, __shfl_xor_sync(0xffffffffu, mx0, 2));
        mx1 = fmaxf(mx1, __shfl_xor_sync(0xffffffffu, mx1, 1));
        mx1 = fmaxf(mx1, __shfl_xor_sync(0xffffffffu, mx1, 2));

        float mn0 = fmaxf(m0, mx0), mn1 = fmaxf(m1, mx1);
        float al0 = __expf(m0 - mn0), al1 = __expf(m1 - mn1);
        float sum0 = 0.f, sum1 = 0.f;
        #pragma unroll
        for (int nt = 0; nt < 8; nt++) {
            float p00 = __expf(S[nt][0] - mn0);
            float p01 = __expf(S[nt][1] - mn0);
            float p10 = __expf(S[nt][2] - mn1);
            float p11 = __expf(S[nt][3] - mn1);
            sum0 += p00 + p01;
            sum1 += p10 + p11;
            float2 w0 = make_float2(p00, p01);
            float2 w1 = make_float2(p10, p11);
            *(float2*)&Ps[(rbase + g) * ALD + nt * 8 + 2 * q] = w0;
            *(float2*)&Ps[(rbase + g + 8) * ALD + nt * 8 + 2 * q] = w1;
        }
        sum0 += __shfl_xor_sync(0xffffffffu, sum0, 1);
        sum0 += __shfl_xor_sync(0xffffffffu, sum0, 2);
        sum1 += __shfl_xor_sync(0xffffffffu, sum1, 1);
        sum1 += __shfl_xor_sync(0xffffffffu, sum1, 2);
        l0 = l0 * al0 + sum0;
        l1 = l1 * al1 + sum1;
        m0 = mn0; m1 = mn1;
        #pragma unroll
        for (int dt = 0; dt < 8; dt++) {
            Oa[dt][0] *= al0; Oa[dt][1] *= al0;
            Oa[dt][2] *= al1; Oa[dt][3] *= al1;
        }

        for (int idx = t; idx < 1024; idx += 128) {
            int key = idx >> 4;
            int d4 = (idx & 15) << 2;
            float4 v = *(const float4*)(Vb + (size_t)(kTok + key) * 768 + hOff + d4);
            KVs[(d4 + 0) * ALD + key] = v.x;
            KVs[(d4 + 1) * ALD + key] = v.y;
            KVs[(d4 + 2) * ALD + key] = v.z;
            KVs[(d4 + 3) * ALD + key] = v.w;
        }
        __syncthreads();

        #pragma unroll
        for (int kk = 0; kk < 64; kk += 8) {
            uint32_t af[4];
            af[0] = f2tf(Ps[(rbase + g) * ALD + kk + q]);
            af[1] = f2tf(Ps[(rbase + g + 8) * ALD + kk + q]);
            af[2] = f2tf(Ps[(rbase + g) * ALD + kk + 4 + q]);
            af[3] = f2tf(Ps[(rbase + g + 8) * ALD + kk + 4 + q]);
            #pragma unroll
            for (int dt = 0; dt < 8; dt++) {
                uint32_t bf[2];
                bf[0] = f2tf(KVs[(dt * 8 + g) * ALD + kk + q]);
                bf[1] = f2tf(KVs[(dt * 8 + g) * ALD + kk + 4 + q]);
                mma_tf32(Oa[dt], af, bf);
            }
        }
        __syncthreads();
    }

    float inv0 = 1.f / l0, inv1 = 1.f / l1;
    float* orow0 = Ob + (size_t)(qTok + rbase + g) * 768 + hOff;
    float* orow1 = Ob + (size_t)(qTok + rbase + g + 8) * 768 + hOff;
    #pragma unroll
    for (int dt = 0; dt < 8; dt++) {
        int col = dt * 8 + 2 * q;
        *(float2*)(orow0 + col) = make_float2(Oa[dt][0] * inv0, Oa[dt][1] * inv0);
        *(float2*)(orow1 + col) = make_float2(Oa[dt][2] * inv1, Oa[dt][3] * inv1);
    }
}

// ---------------------------------------------------------------------------
// Launch sequence
// ---------------------------------------------------------------------------
extern "C" void kernel_launch(void* const* d_in, const int* in_sizes, int n_in,
                              void* d_out, int out_size)
{
    (void)in_sizes; (void)out_size;
    const float* x       = (const float*)d_in[0];
    const float* ln1_g   = (const float*)d_in[1];
    const float* ln1_b   = (const float*)d_in[2];
    const float* ln2_g   = (const float*)d_in[3];
    const float* ln2_b   = (const float*)d_in[4];
    const float* a1_wqkv = (const float*)d_in[5];
    const float* a1_bqkv = (const float*)d_in[6];
    const float* a1_wo   = (const float*)d_in[7];
    const float* a1_bo   = (const float*)d_in[8];
    const float* a2_wqkv = (const float*)d_in[9];
    const float* a2_bqkv = (const float*)d_in[10];
    const float* a2_wo   = (const float*)d_in[11];
    const float* a2_bo   = (const float*)d_in[12];
    const float* fc_w    = (const float*)d_in[13];
    const float* fc_b    = (const float*)d_in[14];
    const float* proj_w  = (const float*)d_in[15];
    const float* proj_b  = (const float*)d_in[16];
    const int*   idxp    = (n_in > 17) ? (const int*)d_in[17] : nullptr;
    float* out = (float*)d_out;

    float *y, *qkv, *o, *x2, *h;
    cudaGetSymbolAddress((void**)&y,  g_y);
    cudaGetSymbolAddress((void**)&qkv, g_qkv);
    cudaGetSymbolAddress((void**)&o,  g_o);
    cudaGetSymbolAddress((void**)&x2, g_x2);
    cudaGetSymbolAddress((void**)&h,  g_h);

    const int AS = 3 * 64 * ALD * 4;   // 52224 B
    cudaFuncSetAttribute(attn_kernel,
                         cudaFuncAttributeMaxDynamicSharedMemorySize, AS);
    cudaFuncSetAttribute(tgemm_kernel,
                         cudaFuncAttributeMaxDynamicSharedMemorySize, 73728);

    const size_t SZ = QKV_SZ;
    const int WQ = 589824;     // 768*768
    const int GS = 73728;

    // 1) y = LN1(x)
    ln_kernel<<<65536, 192>>>(x, ln1_g, ln1_b, y);

    // 2) QKV projections (compact per-view outputs)
    tgemm_kernel<<<dim3(6, 256), 256, GS>>>(y, a1_wqkv,          a1_bqkv,        qkv + 0 * SZ, nullptr, 768, 768,  0,  0, -1, 0, idxp);
    tgemm_kernel<<<dim3(6, 256), 256, GS>>>(y, a2_wqkv,          a2_bqkv,        qkv + 1 * SZ, nullptr, 768, 768,  1,  0, -1, 0, idxp);
    tgemm_kernel<<<dim3(6, 256), 256, GS>>>(y, a1_wqkv + WQ,     a1_bqkv + 768,  qkv + 2 * SZ, nullptr, 768, 768,  1,  0, -1, 0, idxp);
    tgemm_kernel<<<dim3(6, 256), 256, GS>>>(y, a2_wqkv + WQ,     a2_bqkv + 768,  qkv + 3 * SZ, nullptr, 768, 768,  0,  0, -1, 0, idxp);
    tgemm_kernel<<<dim3(6, 256), 256, GS>>>(x, a1_wqkv + 2 * WQ, a1_bqkv + 1536, qkv + 4 * SZ, nullptr, 768, 768,  0, -1, -1, 0, idxp);
    tgemm_kernel<<<dim3(6, 256), 256, GS>>>(x, a2_wqkv + 2 * WQ, a2_bqkv + 1536, qkv + 5 * SZ, nullptr, 768, 768,  1, -1, -1, 0, idxp);

    // 3) windowed flash attention (tensor cores)
    attn_kernel<<<dim3(8, 12, 128), 128, AS>>>();

    // 4) out-proj + un-roll + residual
    tgemm_kernel<<<dim3(6, 256), 256, GS>>>(o,      a1_wo, a1_bo, x2, x, 768, 768, -2, +1, 0, 0, idxp);
    tgemm_kernel<<<dim3(6, 256), 256, GS>>>(o + SZ, a2_wo, a2_bo, x2, x, 768, 768, -2, +1, 1, 0, idxp);

    // 5) y = LN2(x2)
    ln_kernel<<<65536, 192>>>(x2, ln2_g, ln2_b, y);

    // 6) h = gelu(y @ fc_w.T + fc_b)
    tgemm_kernel<<<dim3(24, 512), 256, GS>>>(y, fc_w, fc_b, h, nullptr, 768, 3072, -1, 0, -1, 1, idxp);

    // 7) out = x2 + h @ proj_w.T + proj_b
    tgemm_kernel<<<dim3(6, 512), 256, GS>>>(h, proj_w, proj_b, out, x2, 3072, 768, -1, 0, -1, 0, idxp);
}